// round 16
// baseline (speedup 1.0000x reference)
#include <cuda_runtime.h>
#include <cuda_bf16.h>
#include <cstdint>

#define BB 4
#define SS 1024
#define DD 1024
#define HH 16
#define DKK 64
#define DVV 32
#define BH (BB*HH)          // 64
#define MM (BB*SS)          // 4096
#define CDIM (HH*DVV)       // 512
#define NQKV (HH*160)       // 2560

// A-side packed bf16x2 split operands (separate hi/lo planes: ldmatrix)
__device__ uint32_t XH[MM*512],  XL[MM*512];
__device__ uint32_t QH[BH*SS*32], QL[BH*SS*32];
__device__ uint32_t GCH[MM*256],  GCL[MM*256];
// B-side interleaved (hi in low word, lo in high word) for LDS.64
__device__ uint64_t WI[(size_t)512*NQKV];
__device__ uint64_t WOI[256*DD];
__device__ uint64_t KI[BH*SS*32];
__device__ uint64_t VI[BH*512*32];

// ---------------------------------------------------------------------------
__device__ __forceinline__ uint32_t smem_u32(const void* p){
    return (uint32_t)__cvta_generic_to_shared(p);
}
__device__ __forceinline__ void cp16(uint32_t dst, const void* src){
    asm volatile("cp.async.cg.shared.global [%0], [%1], 16;\n" :: "r"(dst), "l"(src));
}
__device__ __forceinline__ void cp_commit(){ asm volatile("cp.async.commit_group;\n"); }
template<int N> __device__ __forceinline__ void cp_wait(){
    asm volatile("cp.async.wait_group %0;\n" :: "n"(N));
}
__device__ __forceinline__ void mma_bf16(float* d, const uint32_t* a, const uint32_t* b){
    asm volatile(
      "mma.sync.aligned.m16n8k16.row.col.f32.bf16.bf16.f32 "
      "{%0,%1,%2,%3},{%4,%5,%6,%7},{%8,%9},{%0,%1,%2,%3};\n"
      : "+f"(d[0]),"+f"(d[1]),"+f"(d[2]),"+f"(d[3])
      : "r"(a[0]),"r"(a[1]),"r"(a[2]),"r"(a[3]),"r"(b[0]),"r"(b[1]));
}
__device__ __forceinline__ void ldsm_x4(uint32_t* d, uint32_t saddr){
    asm volatile("ldmatrix.sync.aligned.m8n8.x4.shared.b16 {%0,%1,%2,%3}, [%4];"
        : "=r"(d[0]),"=r"(d[1]),"=r"(d[2]),"=r"(d[3]) : "r"(saddr));
}
__device__ __forceinline__ uint32_t b2u(__nv_bfloat162 h){
    return *reinterpret_cast<uint32_t*>(&h);
}
__device__ __forceinline__ float2 u2f2(uint32_t u){
    __nv_bfloat162 h = *reinterpret_cast<__nv_bfloat162*>(&u);
    return __bfloat1622float2(h);
}
__device__ __forceinline__ void pack_split(float v0, float v1, uint32_t& hi, uint32_t& lo){
    __nv_bfloat162 h = __floats2bfloat162_rn(v0, v1);
    hi = b2u(h);
    float r0 = v0 - __bfloat162float(h.x);
    float r1 = v1 - __bfloat162float(h.y);
    lo = b2u(__floats2bfloat162_rn(r0, r1));
}
__device__ __forceinline__ uint64_t pk64(uint32_t hi, uint32_t lo){
    return ((uint64_t)lo << 32) | (uint64_t)hi;
}
// one-shot producer->consumer mbarrier helpers
__device__ __forceinline__ void mbar_init(uint32_t addr, uint32_t count){
    asm volatile("mbarrier.init.shared.b64 [%0], %1;" :: "r"(addr), "r"(count) : "memory");
}
__device__ __forceinline__ void mbar_arrive(uint32_t addr){
    asm volatile("mbarrier.arrive.release.cta.shared::cta.b64 _, [%0];" :: "r"(addr) : "memory");
}
__device__ __forceinline__ void mbar_wait0(uint32_t addr){
    uint32_t done;
    asm volatile(
        "{\n\t.reg .pred p;\n\t"
        "mbarrier.try_wait.parity.acquire.cta.shared::cta.b64 p, [%1], 0;\n\t"
        "selp.b32 %0, 1, 0, p;\n\t}"
        : "=r"(done) : "r"(addr) : "memory");
    while (!done) {
        asm volatile(
            "{\n\t.reg .pred p;\n\t"
            "mbarrier.try_wait.parity.acquire.cta.shared::cta.b64 p, [%1], 0, 0x989680;\n\t"
            "selp.b32 %0, 1, 0, p;\n\t}"
            : "=r"(done) : "r"(addr) : "memory");
    }
}
#define PROD_BAR() asm volatile("bar.sync 1, 256;" ::: "memory")
#define CONS_BAR() asm volatile("bar.sync 2, 256;" ::: "memory")

// ---------------------------------------------------------------------------
// K0: presplit x (planes), fused W (interleaved), Wo (interleaved)
// ---------------------------------------------------------------------------
__global__ void presplit(const float* __restrict__ x,
                         const float* __restrict__ Wq, const float* __restrict__ Wk,
                         const float* __restrict__ Wv, const float* __restrict__ Wo)
{
    const int nth = gridDim.x * blockDim.x;
    const int t0  = blockIdx.x * blockDim.x + threadIdx.x;
    for (int idx = t0; idx < MM*512; idx += nth) {
        int row = idx >> 9, cp = idx & 511;
        float2 v = *(const float2*)&x[(size_t)row * DD + 2*cp];
        pack_split(v.x, v.y, XH[idx], XL[idx]);
    }
    for (size_t idx = t0; idx < (size_t)512*NQKV; idx += nth) {
        int kp = (int)(idx / NQKV), gn = (int)(idx - (size_t)kp * NQKV);
        int h = gn / 160, off = gn - h * 160;
        int d0 = 2*kp, d1 = 2*kp + 1;
        float w0, w1;
        if (off < 64) {
            w0 = Wq[((size_t)h*DD + d0)*DKK + off];
            w1 = Wq[((size_t)h*DD + d1)*DKK + off];
        } else if (off < 128) {
            w0 = Wk[((size_t)h*DD + d0)*DKK + off - 64];
            w1 = Wk[((size_t)h*DD + d1)*DKK + off - 64];
        } else {
            w0 = Wv[((size_t)h*DD + d0)*DVV + off - 128];
            w1 = Wv[((size_t)h*DD + d1)*DVV + off - 128];
        }
        uint32_t hi, lo;
        pack_split(w0, w1, hi, lo);
        WI[idx] = pk64(hi, lo);
    }
    for (int idx = t0; idx < 256*DD; idx += nth) {
        int kp = idx >> 10, n = idx & 1023;
        float w0 = Wo[(size_t)(2*kp)*DD + n];
        float w1 = Wo[(size_t)(2*kp + 1)*DD + n];
        uint32_t hi, lo;
        pack_split(w0, w1, hi, lo);
        WOI[idx] = pk64(hi, lo);
    }
}

// ---------------------------------------------------------------------------
// K1: QKV projection — 3-stage ring, 1 sync/iter, 2 CTAs/SM,
// A via ldmatrix (planes), B via LDS.64 (interleaved).
// ---------------------------------------------------------------------------
#define PA_STR 20
#define PB2_STR 132                 // u64 per B row (128 + pad4; pad%16==4)
#define PA_SZ (128*PA_STR)          // u32
#define PB2_SZ (16*PB2_STR*2)       // in u32 units = 4224
#define PSTG (2*PA_SZ + PB2_SZ)     // 9344 u32 per stage (37376 B)

__global__ void __launch_bounds__(512,2) proj_bf16(
    const float* __restrict__ bq, const float* __restrict__ bk,
    const float* __restrict__ bv)
{
    extern __shared__ uint32_t sm32[];
    const int tid  = threadIdx.x;
    const int lane = tid & 31, warp = tid >> 5;
    const int wm = warp & 3, wn = warp >> 2;
    const int r = lane & 3, g = lane >> 2;
    const int m0 = blockIdx.x * 128;
    const int n0 = blockIdx.y * 128;
    uint32_t sb = smem_u32(sm32);

    const int lrow0 = wm * 32 + (lane & 7) + ((lane >> 3) & 1) * 8;
    const int lcol4 = (lane >> 4) * 4;

    float acc[2][4][4];
    #pragma unroll
    for (int mt = 0; mt < 2; mt++)
        #pragma unroll
        for (int nt = 0; nt < 4; nt++)
            #pragma unroll
            for (int i = 0; i < 4; i++) acc[mt][nt][i] = 0.f;

    auto issue_load = [&](int s, int it) {
        uint32_t base = sb + (uint32_t)(s * PSTG) * 4u;
        #pragma unroll
        for (int p = 0; p < 2; p++) {
            const uint32_t* src = p ? XL : XH;
            uint32_t dstb = base + (uint32_t)(p * PA_SZ) * 4u;
            int row = tid >> 2, c4 = (tid & 3) * 4;
            cp16(dstb + (uint32_t)(row * PA_STR + c4) * 4u,
                 &src[(size_t)(m0 + row) * 512 + it * 16 + c4]);
        }
        // B interleaved: 16 rows x 128 u64 -> 1024 16B chunks (2 u64 each)
        uint32_t dstb = base + (uint32_t)(2 * PA_SZ) * 4u;
        #pragma unroll
        for (int i = 0; i < 2; i++) {
            int flat = tid + i * 512;
            int kp = flat >> 6, cc = (flat & 63) * 2;
            cp16(dstb + (uint32_t)(kp * PB2_STR + cc) * 8u,
                 &WI[(size_t)(it * 16 + kp) * NQKV + n0 + cc]);
        }
    };

    issue_load(0, 0); cp_commit();
    issue_load(1, 1); cp_commit();

    for (int it = 0; it < 32; it++) {
        if (it + 1 < 32) cp_wait<1>(); else cp_wait<0>();
        __syncthreads();
        if (it + 2 < 32) { issue_load((it + 2) % 3, it + 2); cp_commit(); }

        uint32_t a_h = sb + (uint32_t)((it % 3) * PSTG) * 4u;
        uint32_t a_l = a_h + (uint32_t)PA_SZ * 4u;
        const uint64_t* BI = (const uint64_t*)(sm32 + (it % 3) * PSTG + 2 * PA_SZ);

        #pragma unroll
        for (int kt = 0; kt < 2; kt++) {
            uint32_t ah[2][4], al[2][4], bh2[4][2], bl2[4][2];
            #pragma unroll
            for (int mt = 0; mt < 2; mt++) {
                uint32_t off = (uint32_t)(((lrow0 + mt*16) * PA_STR) + kt*8 + lcol4) * 4u;
                ldsm_x4(ah[mt], a_h + off);
                ldsm_x4(al[mt], a_l + off);
            }
            #pragma unroll
            for (int nt = 0; nt < 4; nt++) {
                int col = wn * 32 + nt * 8 + g;
                uint64_t w0 = BI[(kt * 8 + r) * PB2_STR + col];
                uint64_t w1 = BI[(kt * 8 + r + 4) * PB2_STR + col];
                bh2[nt][0] = (uint32_t)w0; bl2[nt][0] = (uint32_t)(w0 >> 32);
                bh2[nt][1] = (uint32_t)w1; bl2[nt][1] = (uint32_t)(w1 >> 32);
            }
            #pragma unroll
            for (int mt = 0; mt < 2; mt++)
                #pragma unroll
                for (int nt = 0; nt < 4; nt++) {
                    mma_bf16(acc[mt][nt], ah[mt], bh2[nt]);
                    mma_bf16(acc[mt][nt], ah[mt], bl2[nt]);
                    mma_bf16(acc[mt][nt], al[mt], bh2[nt]);
                }
        }
    }

    // fused epilogue: Q -> planes (ldmatrix consumer); K,V -> interleaved u64
    #pragma unroll
    for (int mt = 0; mt < 2; mt++) {
        int row0 = m0 + wm * 32 + mt * 16 + g;
        int b0_ = row0 >> 10, s0_ = row0 & 1023;
        #pragma unroll
        for (int nt = 0; nt < 4; nt++) {
            int gn = n0 + wn * 32 + nt * 8 + 2 * r;
            int h = gn / 160, off = gn - h * 160;
            uint32_t hi, lo;
            if (off < 64) {
                float bia0 = bq[h*DKK + off], bia1 = bq[h*DKK + off + 1];
                size_t bhs0 = ((size_t)(b0_*HH + h))*SS + s0_;
                int cp = off >> 1;
                pack_split(acc[mt][nt][0] + bia0, acc[mt][nt][1] + bia1, hi, lo);
                QH[bhs0*32 + cp] = hi; QL[bhs0*32 + cp] = lo;
                pack_split(acc[mt][nt][2] + bia0, acc[mt][nt][3] + bia1, hi, lo);
                QH[(bhs0 + 8)*32 + cp] = hi; QL[(bhs0 + 8)*32 + cp] = lo;
            } else if (off < 128) {
                int o = off - 64;
                float bia0 = bk[h*DKK + o], bia1 = bk[h*DKK + o + 1];
                size_t bhs0 = ((size_t)(b0_*HH + h))*SS + s0_;
                int cp = o >> 1;
                pack_split(acc[mt][nt][0] + bia0, acc[mt][nt][1] + bia1, hi, lo);
                KI[bhs0*32 + cp] = pk64(hi, lo);
                pack_split(acc[mt][nt][2] + bia0, acc[mt][nt][3] + bia1, hi, lo);
                KI[(bhs0 + 8)*32 + cp] = pk64(hi, lo);
            } else {
                int dv = off - 128;
                float bia0 = bv[h*DVV + dv], bia1 = bv[h*DVV + dv + 1];
                float v0 = acc[mt][nt][0] + bia0, v1 = acc[mt][nt][1] + bia1;
                float v2 = acc[mt][nt][2] + bia0, v3 = acc[mt][nt][3] + bia1;
                float p0 = __shfl_xor_sync(0xffffffffu, v0, 4);
                float p1 = __shfl_xor_sync(0xffffffffu, v1, 4);
                float p2 = __shfl_xor_sync(0xffffffffu, v2, 4);
                float p3 = __shfl_xor_sync(0xffffffffu, v3, 4);
                if ((g & 1) == 0) {
                    size_t vb = (size_t)(b0_*HH + h) * 512;
                    int kp = s0_ >> 1;
                    pack_split(v0, p0, hi, lo);
                    VI[(vb + kp)*32 + dv] = pk64(hi, lo);
                    pack_split(v1, p1, hi, lo);
                    VI[(vb + kp)*32 + dv + 1] = pk64(hi, lo);
                    pack_split(v2, p2, hi, lo);
                    VI[(vb + kp + 4)*32 + dv] = pk64(hi, lo);
                    pack_split(v3, p3, hi, lo);
                    VI[(vb + kp + 4)*32 + dv + 1] = pk64(hi, lo);
                }
            }
        }
    }
}

// ---------------------------------------------------------------------------
// K3: attention — decoupled roles; K/V smem interleaved u64 (LDS.64 operands);
// scores kept as planes (ldmatrix PV A). Q planes.
// ---------------------------------------------------------------------------
#define QROWS 32
#define SC2_STR 516
#define QT_STR 36                   // u32 stride for Q planes
#define UQ_SZ (QROWS*QT_STR)
#define SCH_SZ (QROWS*SC2_STR)
#define K64_STR 36                  // u64 per key row (32 + pad4)
#define KBUF64 (64*K64_STR)         // 2304 u64 per buffer
#define V64_STR 36
#define VBUF64 (32*V64_STR)         // 1152 u64 per buffer

__global__ void __launch_bounds__(512,1) attn_bf16(float* __restrict__ wout)
{
    extern __shared__ uint32_t sm32[];
    uint32_t* uqh = sm32;
    uint32_t* uql = uqh + UQ_SZ;
    uint32_t* sch = sm32 + 2*UQ_SZ;
    uint32_t* scl = sch + SCH_SZ;
    uint64_t* kb64 = (uint64_t*)(sm32 + 2*UQ_SZ + 2*SCH_SZ);   // 3 x KBUF64
    uint64_t* vb64 = kb64 + 3*KBUF64;                          // 3 x VBUF64
    float*    sinv = (float*)(vb64 + 3*VBUF64);                // 32
    float*    part = sinv + 32;                                // 8 x 32
    uint32_t* mbar = (uint32_t*)(part + 256);                  // 16 x 8B

    const int bh = blockIdx.x, qt = blockIdx.y;
    const int tid = threadIdx.x;
    const int lane = tid & 31, warp = tid >> 5;
    const int r = lane & 3, g = lane >> 2;
    const bool producer = (tid < 256);
    const int ctid = tid - 256;
    const size_t base32 = (size_t)bh * SS + qt * QROWS;
    const size_t kbase32 = (size_t)bh * SS;

    uint32_t uqa = smem_u32(uqh), kba = smem_u32(kb64), vba = smem_u32(vb64);
    uint32_t scha = smem_u32(sch), scla = smem_u32(scl);
    uint32_t mba = smem_u32(mbar);

    if (tid < 16) mbar_init(mba + tid * 8u, 256);
    __syncthreads();

    float phh[4] = {0,0,0,0}, phl[4] = {0,0,0,0}, plh[4] = {0,0,0,0};
    const int w2 = warp - 8;
    const int mtp = w2 & 1, ntp = w2 >> 1;

    if (producer) {
        {
            int row = tid >> 3, c4 = (tid & 7) * 4;
            cp16(uqa + (uint32_t)(row * QT_STR + c4) * 4u, &QH[(base32 + row) * 32 + c4]);
            cp16(uqa + (uint32_t)(UQ_SZ + row * QT_STR + c4) * 4u, &QL[(base32 + row) * 32 + c4]);
            // K chunk 0: 64 keys x 32 u64 = 1024 chunks of 16B -> 4 per thread
            #pragma unroll
            for (int i = 0; i < 4; i++) {
                int flat = tid + i * 256;
                int key = flat >> 4, c2 = (flat & 15) * 2;
                cp16(kba + (uint32_t)(key * K64_STR + c2) * 8u,
                     &KI[(kbase32 + key) * 32 + c2]);
            }
            cp_commit();
        }

        uint32_t qah[2][4][4], qal[2][4][4];
        float psum[2][2] = {{0.f,0.f},{0.f,0.f}};

        for (int kc = 0; kc < 16; kc++) {
            if (kc + 1 < 16) {
                uint32_t dstb = kba + (uint32_t)(((kc + 1) % 3) * KBUF64) * 8u;
                #pragma unroll
                for (int i = 0; i < 4; i++) {
                    int flat = tid + i * 256;
                    int key = flat >> 4, c2 = (flat & 15) * 2;
                    cp16(dstb + (uint32_t)(key * K64_STR + c2) * 8u,
                         &KI[(kbase32 + (kc + 1) * 64 + key) * 32 + c2]);
                }
                cp_commit(); cp_wait<1>();
            } else cp_wait<0>();
            PROD_BAR();

            if (kc == 0) {
                #pragma unroll
                for (int mt = 0; mt < 2; mt++)
                    #pragma unroll
                    for (int kt = 0; kt < 4; kt++) {
                        int a0 = (mt*16 + g) * QT_STR + kt*8 + r;
                        int a1 = (mt*16 + g + 8) * QT_STR + kt*8 + r;
                        qah[mt][kt][0] = uqh[a0]; qah[mt][kt][1] = uqh[a1];
                        qah[mt][kt][2] = uqh[a0+4]; qah[mt][kt][3] = uqh[a1+4];
                        qal[mt][kt][0] = uql[a0]; qal[mt][kt][1] = uql[a1];
                        qal[mt][kt][2] = uql[a0+4]; qal[mt][kt][3] = uql[a1+4];
                    }
            }

            const uint64_t* kbuf = kb64 + (kc % 3) * KBUF64;
            float hh[2][4], hl[2][4], lh[2][4];
            #pragma unroll
            for (int mt = 0; mt < 2; mt++)
                #pragma unroll
                for (int i = 0; i < 4; i++) { hh[mt][i]=0.f; hl[mt][i]=0.f; lh[mt][i]=0.f; }
            #pragma unroll
            for (int kt = 0; kt < 4; kt++) {
                uint32_t bbh[2], bbl[2];
                uint64_t w0 = kbuf[(warp*8 + g) * K64_STR + kt*8 + r];
                uint64_t w1 = kbuf[(warp*8 + g) * K64_STR + kt*8 + r + 4];
                bbh[0] = (uint32_t)w0; bbl[0] = (uint32_t)(w0 >> 32);
                bbh[1] = (uint32_t)w1; bbl[1] = (uint32_t)(w1 >> 32);
                mma_bf16(hh[0], qah[0][kt], bbh);
                mma_bf16(hh[1], qah[1][kt], bbh);
                mma_bf16(hl[0], qah[0][kt], bbl);
                mma_bf16(hl[1], qah[1][kt], bbl);
                mma_bf16(lh[0], qal[0][kt], bbh);
                mma_bf16(lh[1], qal[1][kt], bbh);
            }
            int keyb2 = kc * 32 + warp * 4;
            #pragma unroll
            for (int mt = 0; mt < 2; mt++) {
                float s0 = (hh[mt][0] + hl[mt][0] + lh[mt][0]) * 0.125f;
                float s1 = (hh[mt][1] + hl[mt][1] + lh[mt][1]) * 0.125f;
                float s2 = (hh[mt][2] + hl[mt][2] + lh[mt][2]) * 0.125f;
                float s3 = (hh[mt][3] + hl[mt][3] + lh[mt][3]) * 0.125f;
                float e0 = __expf(s0), e1 = __expf(s1), e2 = __expf(s2), e3 = __expf(s3);
                psum[mt][0] += e0 + e1;
                psum[mt][1] += e2 + e3;
                int row = mt * 16 + g;
                uint32_t hi, lo;
                pack_split(e0, e1, hi, lo);
                sch[row * SC2_STR + keyb2 + r] = hi;
                scl[row * SC2_STR + keyb2 + r] = lo;
                pack_split(e2, e3, hi, lo);
                sch[(row + 8) * SC2_STR + keyb2 + r] = hi;
                scl[(row + 8) * SC2_STR + keyb2 + r] = lo;
            }
            mbar_arrive(mba + (uint32_t)kc * 8u);
        }
        #pragma unroll
        for (int mt = 0; mt < 2; mt++)
            #pragma unroll
            for (int j = 0; j < 2; j++) {
                float s = psum[mt][j];
                s += __shfl_xor_sync(0xffffffffu, s, 1);
                s += __shfl_xor_sync(0xffffffffu, s, 2);
                if (r == 0) part[warp * 32 + mt*16 + j*8 + g] = s;
            }
    } else {
        {
            // V chunk 0: 32 rows x 32 u64 = 512 chunks of 16B -> 2 per thread
            #pragma unroll
            for (int i = 0; i < 2; i++) {
                int flat = ctid + i * 256;
                int kp = flat >> 4, c2 = (flat & 15) * 2;
                cp16(vba + (uint32_t)(kp * V64_STR + c2) * 8u,
                     &VI[((size_t)bh * 512 + kp) * 32 + c2]);
            }
            cp_commit();
        }

        const int srow = mtp * 16 + (lane & 7) + ((lane >> 3) & 1) * 8;
        const int scol4 = (lane >> 4) * 4;

        for (int vc = 0; vc < 16; vc++) {
            if (vc + 1 < 16) {
                uint32_t dstb = vba + (uint32_t)(((vc + 1) % 3) * VBUF64) * 8u;
                #pragma unroll
                for (int i = 0; i < 2; i++) {
                    int flat = ctid + i * 256;
                    int kp = flat >> 4, c2 = (flat & 15) * 2;
                    cp16(dstb + (uint32_t)(kp * V64_STR + c2) * 8u,
                         &VI[((size_t)bh * 512 + (vc + 1) * 32 + kp) * 32 + c2]);
                }
                cp_commit(); cp_wait<1>();
            } else cp_wait<0>();
            CONS_BAR();

            mbar_wait0(mba + (uint32_t)vc * 8u);

            const uint64_t* vbuf = vb64 + (vc % 3) * VBUF64;
            #pragma unroll
            for (int kt = 0; kt < 4; kt++) {
                int kb2 = vc * 32 + kt * 8;
                uint32_t ah[4], al[4];
                uint32_t soff = (uint32_t)(srow * SC2_STR + kb2 + scol4) * 4u;
                ldsm_x4(ah, scha + soff);
                ldsm_x4(al, scla + soff);
                uint32_t bbh[2], bbl[2];
                uint64_t w0 = vbuf[(kt*8 + r) * V64_STR + ntp*8 + g];
                uint64_t w1 = vbuf[(kt*8 + r + 4) * V64_STR + ntp*8 + g];
                bbh[0] = (uint32_t)w0; bbl[0] = (uint32_t)(w0 >> 32);
                bbh[1] = (uint32_t)w1; bbl[1] = (uint32_t)(w1 >> 32);
                mma_bf16(phh, ah, bbh);
                mma_bf16(phl, ah, bbl);
                mma_bf16(plh, al, bbh);
            }
        }
    }

    __syncthreads();
    if (tid < 32) {
        float s = 0.f;
        #pragma unroll
        for (int w = 0; w < 8; w++) s += part[w * 32 + tid];
        sinv[tid] = 1.f / s;
    }
    __syncthreads();

    if (!producer) {
        float pacc[4];
        #pragma unroll
        for (int i = 0; i < 4; i++) pacc[i] = phh[i] + phl[i] + plh[i];
        int row0 = mtp * 16 + g;
        float i0 = sinv[row0], i1 = sinv[row0 + 8];
        int b_ = bh >> 4, h = bh & 15;
        int cp = h * 16 + ntp * 4 + r;
        size_t r0 = (size_t)(b_ * SS + qt * QROWS + row0);
        uint32_t hi, lo;
        pack_split(pacc[0] * i0, pacc[1] * i0, hi, lo);
        GCH[r0 * 256 + cp] = hi; GCL[r0 * 256 + cp] = lo;
        pack_split(pacc[2] * i1, pacc[3] * i1, hi, lo);
        GCH[(r0 + 8) * 256 + cp] = hi; GCL[(r0 + 8) * 256 + cp] = lo;
    }

    #pragma unroll 4
    for (int i = 0; i < 16; i++) {
        int f = tid + i * 512;
        int row = f >> 8, cpp = (f & 255) * 2;
        uint2 h2 = *(const uint2*)(sch + row * SC2_STR + cpp);
        uint2 l2 = *(const uint2*)(scl + row * SC2_STR + cpp);
        float iv = sinv[row];
        float2 w0 = u2f2(h2.x), w1 = u2f2(h2.y);
        float2 d0 = u2f2(l2.x), d1 = u2f2(l2.y);
        float4 v;
        v.x = (w0.x + d0.x) * iv;
        v.y = (w0.y + d0.y) * iv;
        v.z = (w1.x + d1.x) * iv;
        v.w = (w1.y + d1.y) * iv;
        *(float4*)(wout + ((kbase32 + qt * QROWS + row) << 10) + cpp * 2) = v;
    }
}

// ---------------------------------------------------------------------------
// K4: output projection — same structure; A planes (ldmatrix), B LDS.64.
// ---------------------------------------------------------------------------
__global__ void __launch_bounds__(512,2) outproj_bf16(
    const float* __restrict__ bo, float* __restrict__ out)
{
    extern __shared__ uint32_t sm32[];
    const int tid  = threadIdx.x;
    const int lane = tid & 31, warp = tid >> 5;
    const int wm = warp & 3, wn = warp >> 2;
    const int r = lane & 3, g = lane >> 2;
    const int m0 = blockIdx.x * 128;
    const int n0 = blockIdx.y * 128;
    uint32_t sb = smem_u32(sm32);

    const int lrow0 = wm * 32 + (lane & 7) + ((lane >> 3) & 1) * 8;
    const int lcol4 = (lane >> 4) * 4;

    float acc[2][4][4];
    #pragma unroll
    for (int mt = 0; mt < 2; mt++)
        #pragma unroll
        for (int nt = 0; nt < 4; nt++)
            #pragma unroll
            for (int i = 0; i < 4; i++) acc[mt][nt][i] = 0.f;

    auto issue_load = [&](int s, int it) {
        uint32_t base = sb + (uint32_t)(s * PSTG) * 4u;
        #pragma unroll
        for (int p = 0; p < 2; p++) {
            const uint32_t* src = p ? GCL : GCH;
            uint32_t dstb = base + (uint32_t)(p * PA_SZ) * 4u;
            int row = tid >> 2, c4 = (tid & 3) * 4;
            cp16(dstb + (uint32_t)(row * PA_STR + c4) * 4u,
                 &src[(size_t)(m0 + row) * 256 + it * 16 + c4]);
        }
        uint32_t dstb = base + (uint32_t)(2 * PA_SZ) * 4u;
        #pragma unroll
        for (int i = 0; i < 2; i++) {
            int flat = tid + i * 512;
            int kp = flat >> 6, cc = (flat & 63) * 2;
            cp16(dstb + (uint32_t)(kp * PB2_STR + cc) * 8u,
                 &WOI[(size_t)(it * 16 + kp) * DD + n0 + cc]);
        }
    };

    issue_load(0, 0); cp_commit();
    issue_load(1, 1); cp_commit();

    for (int it = 0; it < 16; it++) {
        if (it + 1 < 16) cp_wait<1>(); else cp_wait<0>();
        __syncthreads();
        if (it + 2 < 16) { issue_load((it + 2) % 3, it + 2); cp_commit(); }

        uint32_t a_h = sb + (uint32_t)((it % 3) * PSTG) * 4u;
        uint32_t a_l = a_h + (uint32_t)PA_SZ * 4u;
        const uint64_t* BI = (const uint64_t*)(sm32 + (it % 3) * PSTG + 2 * PA_SZ);

        #pragma unroll
        for (int kt = 0; kt < 2; kt++) {
            uint32_t ah[2][4], al[2][4], bh2[4][2], bl2[4][2];
            #pragma unroll
            for (int mt = 0; mt < 2; mt++) {
                uint32_t off = (uint32_t)(((lrow0 + mt*16) * PA_STR) + kt*8 + lcol4) * 4u;
                ldsm_x4(ah[mt], a_h + off);
                ldsm_x4(al[mt], a_l + off);
            }
            #pragma unroll
            for (int nt = 0; nt < 4; nt++) {
                int col = wn * 32 + nt * 8 + g;
                uint64_t w0 = BI[(kt * 8 + r) * PB2_STR + col];
                uint64_t w1 = BI[(kt * 8 + r + 4) * PB2_STR + col];
                bh2[nt][0] = (uint32_t)w0; bl2[nt][0] = (uint32_t)(w0 >> 32);
                bh2[nt][1] = (uint32_t)w1; bl2[nt][1] = (uint32_t)(w1 >> 32);
            }
            #pragma unroll
            for (int mt = 0; mt < 2; mt++)
                #pragma unroll
                for (int nt = 0; nt < 4; nt++) {
                    mma_bf16(acc[mt][nt], ah[mt], bh2[nt]);
                    mma_bf16(acc[mt][nt], ah[mt], bl2[nt]);
                    mma_bf16(acc[mt][nt], al[mt], bh2[nt]);
                }
        }
    }

    #pragma unroll
    for (int mt = 0; mt < 2; mt++) {
        int row0 = m0 + wm * 32 + mt * 16 + g;
        #pragma unroll
        for (int nt = 0; nt < 4; nt++) {
            int gn = n0 + wn * 32 + nt * 8 + 2 * r;
            float bia0 = bo[gn], bia1 = bo[gn + 1];
            *(float2*)&out[(size_t)row0 * DD + gn] =
                make_float2(acc[mt][nt][0] + bia0, acc[mt][nt][1] + bia1);
            *(float2*)&out[(size_t)(row0 + 8) * DD + gn] =
                make_float2(acc[mt][nt][2] + bia0, acc[mt][nt][3] + bia1);
        }
    }
}

// ---------------------------------------------------------------------------
extern "C" void kernel_launch(void* const* d_in, const int* in_sizes, int n_in,
                              void* d_out, int out_size)
{
    const float* x  = (const float*)d_in[0];
    const float* Wq = (const float*)d_in[1];
    const float* bq = (const float*)d_in[2];
    const float* Wk = (const float*)d_in[3];
    const float* bk = (const float*)d_in[4];
    const float* Wv = (const float*)d_in[5];
    const float* bv = (const float*)d_in[6];
    const float* Wo = (const float*)d_in[7];
    const float* bo = (const float*)d_in[8];

    float* out  = (float*)d_out;
    float* wptr = out + (size_t)BB * SS * DD;

    const int gemm_smem = 3 * PSTG * (int)sizeof(uint32_t);    // 112128 x2 = 224.3KB/SM
    const int attn_smem = (2*UQ_SZ + 2*SCH_SZ) * 4
                          + (3*KBUF64 + 3*VBUF64) * 8
                          + (32 + 256) * 4 + 16 * 8;           // 225536 B

    cudaFuncSetAttribute(proj_bf16,    cudaFuncAttributeMaxDynamicSharedMemorySize, gemm_smem);
    cudaFuncSetAttribute(outproj_bf16, cudaFuncAttributeMaxDynamicSharedMemorySize, gemm_smem);
    cudaFuncSetAttribute(attn_bf16,    cudaFuncAttributeMaxDynamicSharedMemorySize, attn_smem);

    presplit<<<512, 256>>>(x, Wq, Wk, Wv, Wo);
    proj_bf16<<<dim3(MM/128, NQKV/128), 512, gemm_smem>>>(bq, bk, bv);
    attn_bf16<<<dim3(BH, SS/QROWS), 512, attn_smem>>>(wptr);
    outproj_bf16<<<dim3(MM/128, DD/128), 512, gemm_smem>>>(bo, out);
}

// round 17
// speedup vs baseline: 1.0750x; 1.0750x over previous
#include <cuda_runtime.h>
#include <cuda_bf16.h>
#include <cstdint>

#define BB 4
#define SS 1024
#define DD 1024
#define HH 16
#define DKK 64
#define DVV 32
#define BH (BB*HH)          // 64
#define MM (BB*SS)          // 4096
#define CDIM (HH*DVV)       // 512
#define NQKV (HH*160)       // 2560

// packed bf16x2 split operands (hi/lo planes)
__device__ uint32_t XH[MM*512],  XL[MM*512];
__device__ uint32_t WH[512*NQKV], WL[512*NQKV];
__device__ uint32_t WOH[256*DD],  WOL[256*DD];
__device__ uint32_t QH[BH*SS*32], QL[BH*SS*32];
__device__ uint32_t KH[BH*SS*32], KL[BH*SS*32];
__device__ uint32_t VH[BH*512*32], VL[BH*512*32];
__device__ uint32_t GCH[MM*256],  GCL[MM*256];

// ---------------------------------------------------------------------------
__device__ __forceinline__ uint32_t smem_u32(const void* p){
    return (uint32_t)__cvta_generic_to_shared(p);
}
__device__ __forceinline__ void cp16(uint32_t dst, const void* src){
    asm volatile("cp.async.cg.shared.global [%0], [%1], 16;\n" :: "r"(dst), "l"(src));
}
__device__ __forceinline__ void cp_commit(){ asm volatile("cp.async.commit_group;\n"); }
template<int N> __device__ __forceinline__ void cp_wait(){
    asm volatile("cp.async.wait_group %0;\n" :: "n"(N));
}
__device__ __forceinline__ void mma_bf16(float* d, const uint32_t* a, const uint32_t* b){
    asm volatile(
      "mma.sync.aligned.m16n8k16.row.col.f32.bf16.bf16.f32 "
      "{%0,%1,%2,%3},{%4,%5,%6,%7},{%8,%9},{%0,%1,%2,%3};\n"
      : "+f"(d[0]),"+f"(d[1]),"+f"(d[2]),"+f"(d[3])
      : "r"(a[0]),"r"(a[1]),"r"(a[2]),"r"(a[3]),"r"(b[0]),"r"(b[1]));
}
// ldmatrix x4: one 16x16 bf16 tile -> m16n8k16 A fragment
__device__ __forceinline__ void ldsm_x4(uint32_t* d, uint32_t saddr){
    asm volatile("ldmatrix.sync.aligned.m8n8.x4.shared.b16 {%0,%1,%2,%3}, [%4];"
        : "=r"(d[0]),"=r"(d[1]),"=r"(d[2]),"=r"(d[3]) : "r"(saddr));
}
__device__ __forceinline__ uint32_t b2u(__nv_bfloat162 h){
    return *reinterpret_cast<uint32_t*>(&h);
}
__device__ __forceinline__ float2 u2f2(uint32_t u){
    __nv_bfloat162 h = *reinterpret_cast<__nv_bfloat162*>(&u);
    return __bfloat1622float2(h);
}
__device__ __forceinline__ void pack_split(float v0, float v1, uint32_t& hi, uint32_t& lo){
    __nv_bfloat162 h = __floats2bfloat162_rn(v0, v1);
    hi = b2u(h);
    float r0 = v0 - __bfloat162float(h.x);
    float r1 = v1 - __bfloat162float(h.y);
    lo = b2u(__floats2bfloat162_rn(r0, r1));
}
// one-shot producer->consumer mbarrier helpers
__device__ __forceinline__ void mbar_init(uint32_t addr, uint32_t count){
    asm volatile("mbarrier.init.shared.b64 [%0], %1;" :: "r"(addr), "r"(count) : "memory");
}
__device__ __forceinline__ void mbar_arrive(uint32_t addr){
    asm volatile("mbarrier.arrive.release.cta.shared::cta.b64 _, [%0];" :: "r"(addr) : "memory");
}
__device__ __forceinline__ void mbar_wait0(uint32_t addr){
    uint32_t done;
    asm volatile(
        "{\n\t.reg .pred p;\n\t"
        "mbarrier.try_wait.parity.acquire.cta.shared::cta.b64 p, [%1], 0;\n\t"
        "selp.b32 %0, 1, 0, p;\n\t}"
        : "=r"(done) : "r"(addr) : "memory");
    while (!done) {
        asm volatile(
            "{\n\t.reg .pred p;\n\t"
            "mbarrier.try_wait.parity.acquire.cta.shared::cta.b64 p, [%1], 0, 0x989680;\n\t"
            "selp.b32 %0, 1, 0, p;\n\t}"
            : "=r"(done) : "r"(addr) : "memory");
    }
}
#define PROD_BAR() asm volatile("bar.sync 1, 256;" ::: "memory")
#define CONS_BAR() asm volatile("bar.sync 2, 256;" ::: "memory")

// ---------------------------------------------------------------------------
// K0: presplit x, fused W, Wo (full-chip grid)
// ---------------------------------------------------------------------------
__global__ void presplit(const float* __restrict__ x,
                         const float* __restrict__ Wq, const float* __restrict__ Wk,
                         const float* __restrict__ Wv, const float* __restrict__ Wo)
{
    const int nth = gridDim.x * blockDim.x;
    const int t0  = blockIdx.x * blockDim.x + threadIdx.x;
    for (int idx = t0; idx < MM*512; idx += nth) {
        int row = idx >> 9, cp = idx & 511;
        float2 v = *(const float2*)&x[(size_t)row * DD + 2*cp];
        pack_split(v.x, v.y, XH[idx], XL[idx]);
    }
    for (int idx = t0; idx < 512*NQKV; idx += nth) {
        int kp = idx / NQKV, gn = idx - kp * NQKV;
        int h = gn / 160, off = gn - h * 160;
        int d0 = 2*kp, d1 = 2*kp + 1;
        float w0, w1;
        if (off < 64) {
            w0 = Wq[((size_t)h*DD + d0)*DKK + off];
            w1 = Wq[((size_t)h*DD + d1)*DKK + off];
        } else if (off < 128) {
            w0 = Wk[((size_t)h*DD + d0)*DKK + off - 64];
            w1 = Wk[((size_t)h*DD + d1)*DKK + off - 64];
        } else {
            w0 = Wv[((size_t)h*DD + d0)*DVV + off - 128];
            w1 = Wv[((size_t)h*DD + d1)*DVV + off - 128];
        }
        pack_split(w0, w1, WH[idx], WL[idx]);
    }
    for (int idx = t0; idx < 256*DD; idx += nth) {
        int kp = idx >> 10, n = idx & 1023;
        float w0 = Wo[(size_t)(2*kp)*DD + n];
        float w1 = Wo[(size_t)(2*kp + 1)*DD + n];
        pack_split(w0, w1, WOH[idx], WOL[idx]);
    }
}

// ---------------------------------------------------------------------------
// K1: QKV projection — 3-stage ring, 1 sync/iter, 2 CTAs/SM, A via ldmatrix.
// ---------------------------------------------------------------------------
#define PA_STR 20
#define PB_STR 136
#define PA_SZ (128*PA_STR)
#define PB_SZ (16*PB_STR)
#define PSTG (2*PA_SZ + 2*PB_SZ)   // 9472 u32 per stage

__global__ void __launch_bounds__(512,2) proj_bf16(
    const float* __restrict__ bq, const float* __restrict__ bk,
    const float* __restrict__ bv)
{
    extern __shared__ uint32_t sm32[];
    const int tid  = threadIdx.x;
    const int lane = tid & 31, warp = tid >> 5;
    const int wm = warp & 3, wn = warp >> 2;
    const int r = lane & 3, g = lane >> 2;
    const int m0 = blockIdx.x * 128;
    const int n0 = blockIdx.y * 128;
    uint32_t sb = smem_u32(sm32);

    // ldmatrix lane geometry for A fragments
    const int lrow0 = wm * 32 + (lane & 7) + ((lane >> 3) & 1) * 8;   // + mt*16
    const int lcol4 = (lane >> 4) * 4;                                 // + kt*8

    float acc[2][4][4];
    #pragma unroll
    for (int mt = 0; mt < 2; mt++)
        #pragma unroll
        for (int nt = 0; nt < 4; nt++)
            #pragma unroll
            for (int i = 0; i < 4; i++) acc[mt][nt][i] = 0.f;

    auto issue_load = [&](int s, int it) {
        uint32_t base = sb + (uint32_t)(s * PSTG) * 4u;
        #pragma unroll
        for (int p = 0; p < 2; p++) {
            const uint32_t* src = p ? XL : XH;
            uint32_t dstb = base + (uint32_t)(p * PA_SZ) * 4u;
            int row = tid >> 2, c4 = (tid & 3) * 4;
            cp16(dstb + (uint32_t)(row * PA_STR + c4) * 4u,
                 &src[(size_t)(m0 + row) * 512 + it * 16 + c4]);
        }
        #pragma unroll
        for (int p = 0; p < 2; p++) {
            const uint32_t* src = p ? WL : WH;
            uint32_t dstb = base + (uint32_t)(2 * PA_SZ + p * PB_SZ) * 4u;
            int kp = tid >> 5, c = (tid & 31) * 4;
            cp16(dstb + (uint32_t)(kp * PB_STR + c) * 4u,
                 &src[(size_t)(it * 16 + kp) * NQKV + n0 + c]);
        }
    };

    issue_load(0, 0); cp_commit();
    issue_load(1, 1); cp_commit();

    for (int it = 0; it < 32; it++) {
        if (it + 1 < 32) cp_wait<1>(); else cp_wait<0>();
        __syncthreads();
        if (it + 2 < 32) { issue_load((it + 2) % 3, it + 2); cp_commit(); }

        uint32_t a_h = sb + (uint32_t)((it % 3) * PSTG) * 4u;
        uint32_t a_l = a_h + (uint32_t)PA_SZ * 4u;
        const uint32_t* BHs = sm32 + (it % 3) * PSTG + 2 * PA_SZ;
        const uint32_t* BLs = BHs + PB_SZ;

        #pragma unroll
        for (int kt = 0; kt < 2; kt++) {
            uint32_t ah[2][4], al[2][4], bh2[4][2], bl2[4][2];
            #pragma unroll
            for (int mt = 0; mt < 2; mt++) {
                uint32_t off = (uint32_t)(((lrow0 + mt*16) * PA_STR) + kt*8 + lcol4) * 4u;
                ldsm_x4(ah[mt], a_h + off);
                ldsm_x4(al[mt], a_l + off);
            }
            #pragma unroll
            for (int nt = 0; nt < 4; nt++) {
                int col = wn * 32 + nt * 8 + g;
                int b0 = (kt * 8 + r) * PB_STR + col;
                int b1 = (kt * 8 + r + 4) * PB_STR + col;
                bh2[nt][0] = BHs[b0]; bh2[nt][1] = BHs[b1];
                bl2[nt][0] = BLs[b0]; bl2[nt][1] = BLs[b1];
            }
            #pragma unroll
            for (int mt = 0; mt < 2; mt++)
                #pragma unroll
                for (int nt = 0; nt < 4; nt++) {
                    mma_bf16(acc[mt][nt], ah[mt], bh2[nt]);
                    mma_bf16(acc[mt][nt], ah[mt], bl2[nt]);
                    mma_bf16(acc[mt][nt], al[mt], bh2[nt]);
                }
        }
    }

    // fused epilogue: split+pack directly to QH/QL, KH/KL, VH/VL
    #pragma unroll
    for (int mt = 0; mt < 2; mt++) {
        int row0 = m0 + wm * 32 + mt * 16 + g;
        int b0_ = row0 >> 10, s0_ = row0 & 1023;
        #pragma unroll
        for (int nt = 0; nt < 4; nt++) {
            int gn = n0 + wn * 32 + nt * 8 + 2 * r;
            int h = gn / 160, off = gn - h * 160;
            uint32_t hi, lo;
            if (off < 128) {
                const float* bias = (off < 64) ? bq : bk;
                int o = (off < 64) ? off : off - 64;
                uint32_t* DH = (off < 64) ? QH : KH;
                uint32_t* DL = (off < 64) ? QL : KL;
                float bia0 = bias[h*DKK + o], bia1 = bias[h*DKK + o + 1];
                size_t bhs0 = ((size_t)(b0_*HH + h))*SS + s0_;
                int cp = o >> 1;
                pack_split(acc[mt][nt][0] + bia0, acc[mt][nt][1] + bia1, hi, lo);
                DH[bhs0*32 + cp] = hi; DL[bhs0*32 + cp] = lo;
                pack_split(acc[mt][nt][2] + bia0, acc[mt][nt][3] + bia1, hi, lo);
                DH[(bhs0 + 8)*32 + cp] = hi; DL[(bhs0 + 8)*32 + cp] = lo;
            } else {
                int dv = off - 128;
                float bia0 = bv[h*DVV + dv], bia1 = bv[h*DVV + dv + 1];
                float v0 = acc[mt][nt][0] + bia0, v1 = acc[mt][nt][1] + bia1;
                float v2 = acc[mt][nt][2] + bia0, v3 = acc[mt][nt][3] + bia1;
                float p0 = __shfl_xor_sync(0xffffffffu, v0, 4);
                float p1 = __shfl_xor_sync(0xffffffffu, v1, 4);
                float p2 = __shfl_xor_sync(0xffffffffu, v2, 4);
                float p3 = __shfl_xor_sync(0xffffffffu, v3, 4);
                if ((g & 1) == 0) {
                    size_t vb = (size_t)(b0_*HH + h) * 512;
                    int kp = s0_ >> 1;
                    pack_split(v0, p0, hi, lo);
                    VH[(vb + kp)*32 + dv] = hi;     VL[(vb + kp)*32 + dv] = lo;
                    pack_split(v1, p1, hi, lo);
                    VH[(vb + kp)*32 + dv + 1] = hi; VL[(vb + kp)*32 + dv + 1] = lo;
                    pack_split(v2, p2, hi, lo);
                    VH[(vb + kp + 4)*32 + dv] = hi; VL[(vb + kp + 4)*32 + dv] = lo;
                    pack_split(v3, p3, hi, lo);
                    VH[(vb + kp + 4)*32 + dv + 1] = hi; VL[(vb + kp + 4)*32 + dv + 1] = lo;
                }
            }
        }
    }
}

// ---------------------------------------------------------------------------
// K3: attention — decoupled roles; PV A-operand via ldmatrix.
// ---------------------------------------------------------------------------
#define QROWS 32
#define SC2_STR 516
#define T_STR 36
#define UQ_SZ (QROWS*T_STR)
#define SCH_SZ (QROWS*SC2_STR)
#define KBUF_SZ (2*64*T_STR)
#define VBUF_SZ (2*32*T_STR)

__global__ void __launch_bounds__(512,1) attn_bf16(float* __restrict__ wout)
{
    extern __shared__ uint32_t sm32[];
    uint32_t* uqh = sm32;
    uint32_t* uql = uqh + UQ_SZ;
    uint32_t* sch = sm32 + 2*UQ_SZ;
    uint32_t* scl = sch + SCH_SZ;
    uint32_t* kbase = sm32 + 2*UQ_SZ + 2*SCH_SZ;
    uint32_t* vbase = kbase + 3*KBUF_SZ;
    float*    sinv = (float*)(vbase + 3*VBUF_SZ);    // 32
    float*    part = sinv + 32;                      // 8 x 32
    uint32_t* mbar = (uint32_t*)(part + 256);        // 16 mbarriers x 8B

    const int bh = blockIdx.x, qt = blockIdx.y;
    const int tid = threadIdx.x;
    const int lane = tid & 31, warp = tid >> 5;
    const int r = lane & 3, g = lane >> 2;
    const bool producer = (tid < 256);
    const int ctid = tid - 256;
    const size_t base32 = (size_t)bh * SS + qt * QROWS;
    const size_t kbase32 = (size_t)bh * SS;

    uint32_t uqa = smem_u32(uqh), kba = smem_u32(kbase), vba = smem_u32(vbase);
    uint32_t scha = smem_u32(sch), scla = smem_u32(scl);
    uint32_t mba = smem_u32(mbar);

    if (tid < 16) mbar_init(mba + tid * 8u, 256);
    __syncthreads();

    float phh[4] = {0,0,0,0}, phl[4] = {0,0,0,0}, plh[4] = {0,0,0,0};
    const int w2 = warp - 8;
    const int mtp = w2 & 1, ntp = w2 >> 1;

    if (producer) {
        {
            int row = tid >> 3, c4 = (tid & 7) * 4;
            cp16(uqa + (uint32_t)(row * T_STR + c4) * 4u, &QH[(base32 + row) * 32 + c4]);
            cp16(uqa + (uint32_t)(UQ_SZ + row * T_STR + c4) * 4u, &QL[(base32 + row) * 32 + c4]);
            #pragma unroll
            for (int p = 0; p < 2; p++) {
                const uint32_t* src = p ? KL : KH;
                #pragma unroll
                for (int i = 0; i < 2; i++) {
                    int flat = tid + i * 256;
                    int key = flat >> 3, kc4 = (flat & 7) * 4;
                    cp16(kba + (uint32_t)(p * (KBUF_SZ/2) + key * T_STR + kc4) * 4u,
                         &src[(kbase32 + key) * 32 + kc4]);
                }
            }
            cp_commit();
        }

        uint32_t qah[2][4][4], qal[2][4][4];
        float psum[2][2] = {{0.f,0.f},{0.f,0.f}};

        for (int kc = 0; kc < 16; kc++) {
            if (kc + 1 < 16) {
                uint32_t dstb = kba + (uint32_t)(((kc + 1) % 3) * KBUF_SZ) * 4u;
                #pragma unroll
                for (int p = 0; p < 2; p++) {
                    const uint32_t* src = p ? KL : KH;
                    #pragma unroll
                    for (int i = 0; i < 2; i++) {
                        int flat = tid + i * 256;
                        int key = flat >> 3, kc4 = (flat & 7) * 4;
                        cp16(dstb + (uint32_t)(p * (KBUF_SZ/2) + key * T_STR + kc4) * 4u,
                             &src[(kbase32 + (kc + 1) * 64 + key) * 32 + kc4]);
                    }
                }
                cp_commit(); cp_wait<1>();
            } else cp_wait<0>();
            PROD_BAR();

            if (kc == 0) {
                #pragma unroll
                for (int mt = 0; mt < 2; mt++)
                    #pragma unroll
                    for (int kt = 0; kt < 4; kt++) {
                        int a0 = (mt*16 + g) * T_STR + kt*8 + r;
                        int a1 = (mt*16 + g + 8) * T_STR + kt*8 + r;
                        qah[mt][kt][0] = uqh[a0]; qah[mt][kt][1] = uqh[a1];
                        qah[mt][kt][2] = uqh[a0+4]; qah[mt][kt][3] = uqh[a1+4];
                        qal[mt][kt][0] = uql[a0]; qal[mt][kt][1] = uql[a1];
                        qal[mt][kt][2] = uql[a0+4]; qal[mt][kt][3] = uql[a1+4];
                    }
            }

            const uint32_t* khb = kbase + (kc % 3) * KBUF_SZ;
            const uint32_t* klb = khb + KBUF_SZ/2;
            float hh[2][4], hl[2][4], lh[2][4];
            #pragma unroll
            for (int mt = 0; mt < 2; mt++)
                #pragma unroll
                for (int i = 0; i < 4; i++) { hh[mt][i]=0.f; hl[mt][i]=0.f; lh[mt][i]=0.f; }
            #pragma unroll
            for (int kt = 0; kt < 4; kt++) {
                uint32_t bbh[2], bbl[2];
                int b0 = (warp*8 + g) * T_STR + kt*8 + r;
                bbh[0] = khb[b0]; bbh[1] = khb[b0 + 4];
                bbl[0] = klb[b0]; bbl[1] = klb[b0 + 4];
                mma_bf16(hh[0], qah[0][kt], bbh);
                mma_bf16(hh[1], qah[1][kt], bbh);
                mma_bf16(hl[0], qah[0][kt], bbl);
                mma_bf16(hl[1], qah[1][kt], bbl);
                mma_bf16(lh[0], qal[0][kt], bbh);
                mma_bf16(lh[1], qal[1][kt], bbh);
            }
            int keyb2 = kc * 32 + warp * 4;
            #pragma unroll
            for (int mt = 0; mt < 2; mt++) {
                float s0 = (hh[mt][0] + hl[mt][0] + lh[mt][0]) * 0.125f;
                float s1 = (hh[mt][1] + hl[mt][1] + lh[mt][1]) * 0.125f;
                float s2 = (hh[mt][2] + hl[mt][2] + lh[mt][2]) * 0.125f;
                float s3 = (hh[mt][3] + hl[mt][3] + lh[mt][3]) * 0.125f;
                float e0 = __expf(s0), e1 = __expf(s1), e2 = __expf(s2), e3 = __expf(s3);
                psum[mt][0] += e0 + e1;
                psum[mt][1] += e2 + e3;
                int row = mt * 16 + g;
                uint32_t hi, lo;
                pack_split(e0, e1, hi, lo);
                sch[row * SC2_STR + keyb2 + r] = hi;
                scl[row * SC2_STR + keyb2 + r] = lo;
                pack_split(e2, e3, hi, lo);
                sch[(row + 8) * SC2_STR + keyb2 + r] = hi;
                scl[(row + 8) * SC2_STR + keyb2 + r] = lo;
            }
            mbar_arrive(mba + (uint32_t)kc * 8u);
        }
        #pragma unroll
        for (int mt = 0; mt < 2; mt++)
            #pragma unroll
            for (int j = 0; j < 2; j++) {
                float s = psum[mt][j];
                s += __shfl_xor_sync(0xffffffffu, s, 1);
                s += __shfl_xor_sync(0xffffffffu, s, 2);
                if (r == 0) part[warp * 32 + mt*16 + j*8 + g] = s;
            }
    } else {
        {
            int kp = ctid >> 3, c4 = (ctid & 7) * 4;
            cp16(vba + (uint32_t)(kp * T_STR + c4) * 4u,
                 &VH[((size_t)bh * 512 + kp) * 32 + c4]);
            cp16(vba + (uint32_t)(VBUF_SZ/2 + kp * T_STR + c4) * 4u,
                 &VL[((size_t)bh * 512 + kp) * 32 + c4]);
            cp_commit();
        }

        // ldmatrix lane geometry for score (PV A) fragments
        const int srow = mtp * 16 + (lane & 7) + ((lane >> 3) & 1) * 8;
        const int scol4 = (lane >> 4) * 4;

        for (int vc = 0; vc < 16; vc++) {
            if (vc + 1 < 16) {
                uint32_t dstb = vba + (uint32_t)(((vc + 1) % 3) * VBUF_SZ) * 4u;
                int kp = ctid >> 3, c4 = (ctid & 7) * 4;
                cp16(dstb + (uint32_t)(kp * T_STR + c4) * 4u,
                     &VH[((size_t)bh * 512 + (vc + 1) * 32 + kp) * 32 + c4]);
                cp16(dstb + (uint32_t)(VBUF_SZ/2 + kp * T_STR + c4) * 4u,
                     &VL[((size_t)bh * 512 + (vc + 1) * 32 + kp) * 32 + c4]);
                cp_commit(); cp_wait<1>();
            } else cp_wait<0>();
            CONS_BAR();

            mbar_wait0(mba + (uint32_t)vc * 8u);

            const uint32_t* vhb = vbase + (vc % 3) * VBUF_SZ;
            const uint32_t* vlb = vhb + VBUF_SZ/2;
            #pragma unroll
            for (int kt = 0; kt < 4; kt++) {
                int kb2 = vc * 32 + kt * 8;
                uint32_t ah[4], al[4];
                uint32_t soff = (uint32_t)(srow * SC2_STR + kb2 + scol4) * 4u;
                ldsm_x4(ah, scha + soff);
                ldsm_x4(al, scla + soff);
                uint32_t bbh[2], bbl[2];
                int b0 = (kt*8 + r) * T_STR + ntp*8 + g;
                int b1 = (kt*8 + r + 4) * T_STR + ntp*8 + g;
                bbh[0] = vhb[b0]; bbh[1] = vhb[b1];
                bbl[0] = vlb[b0]; bbl[1] = vlb[b1];
                mma_bf16(phh, ah, bbh);
                mma_bf16(phl, ah, bbl);
                mma_bf16(plh, al, bbh);
            }
        }
    }

    __syncthreads();
    if (tid < 32) {
        float s = 0.f;
        #pragma unroll
        for (int w = 0; w < 8; w++) s += part[w * 32 + tid];
        sinv[tid] = 1.f / s;
    }
    __syncthreads();

    if (!producer) {
        float pacc[4];
        #pragma unroll
        for (int i = 0; i < 4; i++) pacc[i] = phh[i] + phl[i] + plh[i];
        int row0 = mtp * 16 + g;
        float i0 = sinv[row0], i1 = sinv[row0 + 8];
        int b_ = bh >> 4, h = bh & 15;
        int cp = h * 16 + ntp * 4 + r;
        size_t r0 = (size_t)(b_ * SS + qt * QROWS + row0);
        uint32_t hi, lo;
        pack_split(pacc[0] * i0, pacc[1] * i0, hi, lo);
        GCH[r0 * 256 + cp] = hi; GCL[r0 * 256 + cp] = lo;
        pack_split(pacc[2] * i1, pacc[3] * i1, hi, lo);
        GCH[(r0 + 8) * 256 + cp] = hi; GCL[(r0 + 8) * 256 + cp] = lo;
    }

    #pragma unroll 4
    for (int i = 0; i < 16; i++) {
        int f = tid + i * 512;
        int row = f >> 8, cpp = (f & 255) * 2;
        uint2 h2 = *(const uint2*)(sch + row * SC2_STR + cpp);
        uint2 l2 = *(const uint2*)(scl + row * SC2_STR + cpp);
        float iv = sinv[row];
        float2 w0 = u2f2(h2.x), w1 = u2f2(h2.y);
        float2 d0 = u2f2(l2.x), d1 = u2f2(l2.y);
        float4 v;
        v.x = (w0.x + d0.x) * iv;
        v.y = (w0.y + d0.y) * iv;
        v.z = (w1.x + d1.x) * iv;
        v.w = (w1.y + d1.y) * iv;
        *(float4*)(wout + ((kbase32 + qt * QROWS + row) << 10) + cpp * 2) = v;
    }
}

// ---------------------------------------------------------------------------
// K4: output projection — 3-stage ring, 1 sync/iter, 2 CTAs/SM, A via ldmatrix.
// ---------------------------------------------------------------------------
__global__ void __launch_bounds__(512,2) outproj_bf16(
    const float* __restrict__ bo, float* __restrict__ out)
{
    extern __shared__ uint32_t sm32[];
    const int tid  = threadIdx.x;
    const int lane = tid & 31, warp = tid >> 5;
    const int wm = warp & 3, wn = warp >> 2;
    const int r = lane & 3, g = lane >> 2;
    const int m0 = blockIdx.x * 128;
    const int n0 = blockIdx.y * 128;
    uint32_t sb = smem_u32(sm32);

    const int lrow0 = wm * 32 + (lane & 7) + ((lane >> 3) & 1) * 8;
    const int lcol4 = (lane >> 4) * 4;

    float acc[2][4][4];
    #pragma unroll
    for (int mt = 0; mt < 2; mt++)
        #pragma unroll
        for (int nt = 0; nt < 4; nt++)
            #pragma unroll
            for (int i = 0; i < 4; i++) acc[mt][nt][i] = 0.f;

    auto issue_load = [&](int s, int it) {
        uint32_t base = sb + (uint32_t)(s * PSTG) * 4u;
        #pragma unroll
        for (int p = 0; p < 2; p++) {
            const uint32_t* src = p ? GCL : GCH;
            uint32_t dstb = base + (uint32_t)(p * PA_SZ) * 4u;
            int row = tid >> 2, c4 = (tid & 3) * 4;
            cp16(dstb + (uint32_t)(row * PA_STR + c4) * 4u,
                 &src[(size_t)(m0 + row) * 256 + it * 16 + c4]);
        }
        #pragma unroll
        for (int p = 0; p < 2; p++) {
            const uint32_t* src = p ? WOL : WOH;
            uint32_t dstb = base + (uint32_t)(2 * PA_SZ + p * PB_SZ) * 4u;
            int kp = tid >> 5, c = (tid & 31) * 4;
            cp16(dstb + (uint32_t)(kp * PB_STR + c) * 4u,
                 &src[(size_t)(it * 16 + kp) * DD + n0 + c]);
        }
    };

    issue_load(0, 0); cp_commit();
    issue_load(1, 1); cp_commit();

    for (int it = 0; it < 16; it++) {
        if (it + 1 < 16) cp_wait<1>(); else cp_wait<0>();
        __syncthreads();
        if (it + 2 < 16) { issue_load((it + 2) % 3, it + 2); cp_commit(); }

        uint32_t a_h = sb + (uint32_t)((it % 3) * PSTG) * 4u;
        uint32_t a_l = a_h + (uint32_t)PA_SZ * 4u;
        const uint32_t* BHs = sm32 + (it % 3) * PSTG + 2 * PA_SZ;
        const uint32_t* BLs = BHs + PB_SZ;

        #pragma unroll
        for (int kt = 0; kt < 2; kt++) {
            uint32_t ah[2][4], al[2][4], bh2[4][2], bl2[4][2];
            #pragma unroll
            for (int mt = 0; mt < 2; mt++) {
                uint32_t off = (uint32_t)(((lrow0 + mt*16) * PA_STR) + kt*8 + lcol4) * 4u;
                ldsm_x4(ah[mt], a_h + off);
                ldsm_x4(al[mt], a_l + off);
            }
            #pragma unroll
            for (int nt = 0; nt < 4; nt++) {
                int col = wn * 32 + nt * 8 + g;
                int b0 = (kt * 8 + r) * PB_STR + col;
                int b1 = (kt * 8 + r + 4) * PB_STR + col;
                bh2[nt][0] = BHs[b0]; bh2[nt][1] = BHs[b1];
                bl2[nt][0] = BLs[b0]; bl2[nt][1] = BLs[b1];
            }
            #pragma unroll
            for (int mt = 0; mt < 2; mt++)
                #pragma unroll
                for (int nt = 0; nt < 4; nt++) {
                    mma_bf16(acc[mt][nt], ah[mt], bh2[nt]);
                    mma_bf16(acc[mt][nt], ah[mt], bl2[nt]);
                    mma_bf16(acc[mt][nt], al[mt], bh2[nt]);
                }
        }
    }

    #pragma unroll
    for (int mt = 0; mt < 2; mt++) {
        int row0 = m0 + wm * 32 + mt * 16 + g;
        #pragma unroll
        for (int nt = 0; nt < 4; nt++) {
            int gn = n0 + wn * 32 + nt * 8 + 2 * r;
            float bia0 = bo[gn], bia1 = bo[gn + 1];
            *(float2*)&out[(size_t)row0 * DD + gn] =
                make_float2(acc[mt][nt][0] + bia0, acc[mt][nt][1] + bia1);
            *(float2*)&out[(size_t)(row0 + 8) * DD + gn] =
                make_float2(acc[mt][nt][2] + bia0, acc[mt][nt][3] + bia1);
        }
    }
}

// ---------------------------------------------------------------------------
extern "C" void kernel_launch(void* const* d_in, const int* in_sizes, int n_in,
                              void* d_out, int out_size)
{
    const float* x  = (const float*)d_in[0];
    const float* Wq = (const float*)d_in[1];
    const float* bq = (const float*)d_in[2];
    const float* Wk = (const float*)d_in[3];
    const float* bk = (const float*)d_in[4];
    const float* Wv = (const float*)d_in[5];
    const float* bv = (const float*)d_in[6];
    const float* Wo = (const float*)d_in[7];
    const float* bo = (const float*)d_in[8];

    float* out  = (float*)d_out;
    float* wptr = out + (size_t)BB * SS * DD;

    const int gemm_smem = 3 * PSTG * (int)sizeof(uint32_t);   // 113664 x2 = 227.3KB/SM
    const int attn_smem = (2*UQ_SZ + 2*SCH_SZ + 3*KBUF_SZ + 3*VBUF_SZ + 32 + 256)
                          * (int)sizeof(uint32_t) + 16 * 8;   // 225536

    cudaFuncSetAttribute(proj_bf16,    cudaFuncAttributeMaxDynamicSharedMemorySize, gemm_smem);
    cudaFuncSetAttribute(outproj_bf16, cudaFuncAttributeMaxDynamicSharedMemorySize, gemm_smem);
    cudaFuncSetAttribute(attn_bf16,    cudaFuncAttributeMaxDynamicSharedMemorySize, attn_smem);

    presplit<<<1184, 256>>>(x, Wq, Wk, Wv, Wo);
    proj_bf16<<<dim3(MM/128, NQKV/128), 512, gemm_smem>>>(bq, bk, bv);
    attn_bf16<<<dim3(BH, SS/QROWS), 512, attn_smem>>>(wptr);
    outproj_bf16<<<dim3(MM/128, DD/128), 512, gemm_smem>>>(bo, out);
}